// round 1
// baseline (speedup 1.0000x reference)
#include <cuda_runtime.h>
#include <math.h>

#define HW   1024
#define DM   64
#define DS   16
#define NV   25
#define TIN  4

// ---------------- scratch (static device globals; no allocation) ----------------
__device__ float g_state[(size_t)NV * DM * DS * HW];  // drifting-frame SSM state, ~105 MB
__device__ float g_u[TIN * DM * HW];                  // encoder output u (batched over T for encode)
__device__ float g_e1[TIN * DM * HW];                 // encoder hidden
__device__ float g_cc[(DM + 2 * DS) * HW];            // packed: dconv(+bd) | Bv | Cv
__device__ float g_wpack[(DM + 2 * DS) * DM * 9];     // packed wd|wB|wC weights
__device__ float g_bpack[DM + 2 * DS];                // packed bias: bd | 0 | 0
__device__ float g_ymax[DM * HW];                     // max over v of y
__device__ float g_d1[DM * HW];
__device__ float g_d2[DM * HW];

// ---------------- weight/bias packing (once per launch) ----------------
__global__ void pack_w(const float* __restrict__ wd, const float* __restrict__ bd,
                       const float* __restrict__ wB, const float* __restrict__ wC)
{
    int k = blockIdx.x * 256 + threadIdx.x;
    const int W1 = DM * DM * 9;   // 36864
    const int W2 = DS * DM * 9;   // 9216
    if (k < W1)                 g_wpack[k] = wd[k];
    else if (k < W1 + W2)       g_wpack[k] = wB[k - W1];
    else if (k < W1 + 2 * W2)   g_wpack[k] = wC[k - W1 - W2];
    if (k < DM)                 g_bpack[k] = bd[k];
    else if (k < DM + 2 * DS)   g_bpack[k] = 0.f;
}

// ---------------- circular 3x3 conv ----------------
// x: [T][IC][HW], w: [OC][IC][3][3], y: [T][OC][HW]. Block = 128 threads = 128 pixels.
// grid = (HW/128, OC/OGRP, T). Weights for the block's OGRP channels staged in smem
// transposed to [i*9+tap][og] so the inner loads vectorize (LDS.128 broadcast).
template <int IC, int OGRP, bool RELU, bool BIAS>
__global__ void conv3x3(const float* __restrict__ x, const float* __restrict__ wgt,
                        const float* __restrict__ bias, float* __restrict__ y, int OC)
{
    __shared__ float ws[IC * 9 * OGRP];
    const int tid = threadIdx.x;
    const int obase = blockIdx.y * OGRP;
    const int t = blockIdx.z;
    x += (size_t)t * IC * HW;

    for (int k = tid; k < IC * 9 * OGRP; k += 128) {
        int it = k / OGRP, og = k - it * OGRP;
        ws[k] = wgt[(obase + og) * IC * 9 + it];
    }
    __syncthreads();

    const int p = blockIdx.x * 128 + tid;
    const int h = p >> 5, w = p & 31;
    const int hm = ((h + 31) & 31) << 5, h0 = h << 5, hp = ((h + 1) & 31) << 5;
    const int wm = (w + 31) & 31, wp = (w + 1) & 31;

    float acc[OGRP];
#pragma unroll
    for (int og = 0; og < OGRP; og++) acc[og] = BIAS ? bias[obase + og] : 0.f;

    for (int i = 0; i < IC; i++) {
        const float* xi = x + i * HW;
        float xv[9];
        xv[0] = xi[hm + wm]; xv[1] = xi[hm + w]; xv[2] = xi[hm + wp];
        xv[3] = xi[h0 + wm]; xv[4] = xi[h0 + w]; xv[5] = xi[h0 + wp];
        xv[6] = xi[hp + wm]; xv[7] = xi[hp + w]; xv[8] = xi[hp + wp];
        const float* wrow = &ws[i * 9 * OGRP];
#pragma unroll
        for (int tap = 0; tap < 9; tap++)
#pragma unroll
            for (int og = 0; og < OGRP; og++)
                acc[og] = fmaf(xv[tap], wrow[tap * OGRP + og], acc[og]);
    }

#pragma unroll
    for (int og = 0; og < OGRP; og++) {
        float v = RELU ? fmaxf(acc[og], 0.f) : acc[og];
        y[((size_t)t * OC + obase + og) * HW + p] = v;
    }
}

// ---------------- fused SSM cell step (drifting frame, in-place state) ----------------
// Thread owns coefficient position p for channel d. It computes delta/A_bar/Bu/Cv in
// registers, then for each velocity v updates sigma at q = p + tau*delta_v in place,
// accumulating y[v] = sum_n s*Cv and the running max over v.
// grid = (8, 64) blocks of 128 threads.
template <bool FIRST, bool DOY>
__global__ void cell_step(const float* __restrict__ u,
                          const float* __restrict__ logA,
                          const float* __restrict__ Dskip,
                          const float* __restrict__ dtp,
                          int tau, float* __restrict__ ymax)
{
    const int d = blockIdx.y;
    const int p = blockIdx.x * 128 + threadIdx.x;
    const int h = p >> 5, w = p & 31;

    const float dt_inv = dtp[0];
    float xx = g_cc[d * HW + p] + dt_inv;
    float delta = (xx > 20.f) ? xx : log1pf(expf(xx));   // softplus
    const float udp = u[d * HW + p];

    float ab[DS], bu[DS], cv[DS];
#pragma unroll
    for (int n = 0; n < DS; n++) {
        float a = -expf(logA[d * DS + n]);
        float e = expf(delta * a);
        ab[n] = e;
        bu[n] = (e - 1.f) / a * g_cc[(DM + n) * HW + p] * udp;
        if (DOY) cv[n] = g_cc[(DM + DS + n) * HW + p];
    }

    float best = -1e30f;
#pragma unroll 1
    for (int v = 0; v < NV; v++) {
        int v5 = v / 5;
        int vx = v5 - 2;
        int vy = (v - v5 * 5) - 2;
        int qh = (h + tau * vy) & 31;
        int qw = (w + tau * vx) & 31;
        float* sp = g_state + (size_t)(v * DM + d) * DS * HW + (qh << 5) + qw;
        float acc = 0.f;
#pragma unroll
        for (int n = 0; n < DS; n++) {
            float s = FIRST ? bu[n] : fmaf(ab[n], sp[n * HW], bu[n]);
            sp[n * HW] = s;
            if (DOY) acc = fmaf(s, cv[n], acc);
        }
        if (DOY) best = fmaxf(best, acc);
    }
    if (DOY) ymax[d * HW + p] = fmaf(Dskip[d], udp, best);
}

// ---------------- launch ----------------
extern "C" void kernel_launch(void* const* d_in, const int* in_sizes, int n_in,
                              void* d_out, int out_size)
{
    const float* input_seq = (const float*)d_in[0];
    const float* enc_w1 = (const float*)d_in[1];
    const float* enc_b1 = (const float*)d_in[2];
    const float* enc_w2 = (const float*)d_in[3];
    const float* enc_b2 = (const float*)d_in[4];
    const float* wd     = (const float*)d_in[5];
    const float* bd     = (const float*)d_in[6];
    const float* wB     = (const float*)d_in[7];
    const float* wC     = (const float*)d_in[8];
    const float* logA   = (const float*)d_in[9];
    const float* Dskip  = (const float*)d_in[10];
    const float* dt_inv = (const float*)d_in[11];
    const float* dec_w1 = (const float*)d_in[12];
    const float* dec_b1 = (const float*)d_in[13];
    const float* dec_w2 = (const float*)d_in[14];
    const float* dec_b2 = (const float*)d_in[15];
    const float* dec_w3 = (const float*)d_in[16];
    const float* dec_b3 = (const float*)d_in[17];
    float* out = (float*)d_out;

    float *p_u, *p_e1, *p_cc, *p_wpack, *p_bpack, *p_ymax, *p_d1, *p_d2;
    cudaGetSymbolAddress((void**)&p_u, g_u);
    cudaGetSymbolAddress((void**)&p_e1, g_e1);
    cudaGetSymbolAddress((void**)&p_cc, g_cc);
    cudaGetSymbolAddress((void**)&p_wpack, g_wpack);
    cudaGetSymbolAddress((void**)&p_bpack, g_bpack);
    cudaGetSymbolAddress((void**)&p_ymax, g_ymax);
    cudaGetSymbolAddress((void**)&p_d1, g_d1);
    cudaGetSymbolAddress((void**)&p_d2, g_d2);

    dim3 blk(128);

    // pack wd|wB|wC weights + bias once
    pack_w<<<216, 256>>>(wd, bd, wB, wC);

    // ---- encode phase: batched encoder over T_IN frames ----
    conv3x3<1, 4, true, true><<<dim3(8, 16, TIN), blk>>>(input_seq, enc_w1, enc_b1, p_e1, DM);
    conv3x3<DM, 4, true, true><<<dim3(8, 16, TIN), blk>>>(p_e1, enc_w2, enc_b2, p_u, DM);

    for (int t = 0; t < TIN; t++) {
        const float* ut = p_u + (size_t)t * DM * HW;
        conv3x3<DM, 4, false, true><<<dim3(8, 24, 1), blk>>>(ut, p_wpack, p_bpack, p_cc, DM + 2 * DS);
        if (t == 0)
            cell_step<true, false><<<dim3(8, 64), blk>>>(ut, logA, Dskip, dt_inv, 1, nullptr);
        else
            cell_step<false, false><<<dim3(8, 64), blk>>>(ut, logA, Dskip, dt_inv, t + 1, nullptr);
    }

    // ---- decode phase ----
    int steps = out_size / HW;
    for (int t = 0; t < steps; t++) {
        const float* src = (t == 0) ? (input_seq + 3 * HW) : (out + (size_t)(t - 1) * HW);
        conv3x3<1, 4, true, true><<<dim3(8, 16, 1), blk>>>(src, enc_w1, enc_b1, p_e1, DM);
        conv3x3<DM, 4, true, true><<<dim3(8, 16, 1), blk>>>(p_e1, enc_w2, enc_b2, p_u, DM);
        conv3x3<DM, 4, false, true><<<dim3(8, 24, 1), blk>>>(p_u, p_wpack, p_bpack, p_cc, DM + 2 * DS);
        cell_step<false, true><<<dim3(8, 64), blk>>>(p_u, logA, Dskip, dt_inv, TIN + 1 + t, p_ymax);
        conv3x3<DM, 4, true, true><<<dim3(8, 16, 1), blk>>>(p_ymax, dec_w1, dec_b1, p_d1, DM);
        conv3x3<DM, 4, true, true><<<dim3(8, 16, 1), blk>>>(p_d1, dec_w2, dec_b2, p_d2, DM);
        conv3x3<DM, 1, false, true><<<dim3(8, 1, 1), blk>>>(p_d2, dec_w3, dec_b3, out + (size_t)t * HW, 1);
    }
}

// round 2
// speedup vs baseline: 2.0284x; 2.0284x over previous
#include <cuda_runtime.h>
#include <math.h>

#define HW   1024
#define DM   64
#define DS   16
#define NV   25
#define TIN  4

// ---------------- scratch (static device globals; no allocation) ----------------
// state: drifting frame, layout [v][n][q][d]  (channel-last, warp = 32 d coalesced)
__device__ float g_state[(size_t)NV * DS * HW * DM];   // ~105 MB
__device__ float g_u[TIN * HW * DM];                   // encoder out, [t][px][d]
__device__ float g_e1[TIN * HW * DM];
__device__ float g_cc[TIN * HW * 96];                  // [t][px][dconv|B|C]
__device__ float g_wpack[96 * DM * 9];                 // wd|wB|wC in [oc][ic][9]
__device__ float g_bpack[96];
__device__ float g_A[DS * DM];                         // A[n][d] = -exp(logA[d][n])
__device__ float g_rA[DS * DM];                        // 1/A
__device__ float g_ymax[HW * DM];
__device__ float g_d1[HW * DM];
__device__ float g_d2[HW * DM];

// ---------------- pack weights + A fields (once per launch) ----------------
__global__ void pack_w(const float* __restrict__ wd, const float* __restrict__ bd,
                       const float* __restrict__ wB, const float* __restrict__ wC,
                       const float* __restrict__ logA)
{
    int k = blockIdx.x * 256 + threadIdx.x;
    const int W1 = DM * DM * 9;   // 36864
    const int W2 = DS * DM * 9;   // 9216
    if (k < W1)                 g_wpack[k] = wd[k];
    else if (k < W1 + W2)       g_wpack[k] = wB[k - W1];
    else if (k < W1 + 2 * W2)   g_wpack[k] = wC[k - W1 - W2];
    if (k < DM)                 g_bpack[k] = bd[k];
    else if (k < 96)            g_bpack[k] = 0.f;
    if (k < DS * DM) {
        int n = k >> 6, d = k & 63;
        float a = -expf(logA[d * DS + n]);
        g_A[k] = a;
        g_rA[k] = 1.f / a;
    }
}

// ---------------- channel-last circular 3x3 conv, IC=64 ----------------
// x: [z][px][64], y: [z][px][OC]. Block = 64 threads = 32 px (1 row) x 2 oc-pairs.
// Block covers 4 output channels; thread computes 2. grid = (32 rows, OC/4, z).
// smem: 3 halo rows of x (ic-vectorized, padded to 17 float4 to kill bank conflicts)
// + 4 oc of weights transposed to [oc][tap][ic] (warp-broadcast reads).
template <bool RELU>
__global__ __launch_bounds__(64) void conv_cl(const float* __restrict__ x,
                                              const float* __restrict__ wgt,
                                              const float* __restrict__ bias,
                                              float* __restrict__ y, int OC)
{
    __shared__ float4 xs[3 * 32 * 17];     // 26 KB
    __shared__ float  ws[4][9][64];        // 9 KB
    __shared__ float  bs[4];
    const int tid = threadIdx.x;
    const int obase = blockIdx.y * 4;
    const int r0 = blockIdx.x;
    x += (size_t)blockIdx.z * DM * HW;
    y += (size_t)blockIdx.z * (size_t)OC * HW;

    // stage x: rows r0-1 .. r0+1
    const float4* x4 = (const float4*)x;
    for (int k = tid; k < 3 * 32 * 16; k += 64) {
        int lr = k >> 9; int rem = k & 511; int c = rem >> 4; int icv = rem & 15;
        int row = (r0 - 1 + lr) & 31;
        xs[(lr * 32 + c) * 17 + icv] = x4[(((row << 5) + c) << 4) + icv];
    }
    // stage w transposed: ws[ocl][tap][ic] = w[(obase+ocl)][ic][tap]
    for (int k = tid; k < 4 * 9 * 64; k += 64) {
        int ocl = k / 576; int rem = k - ocl * 576; int tap = rem >> 6; int ic = rem & 63;
        ws[ocl][tap][ic] = wgt[(obase + ocl) * 576 + ic * 9 + tap];
    }
    if (tid < 4) bs[tid] = bias[obase + tid];
    __syncthreads();

    const int ocp = tid >> 5;          // 0..1
    const int c   = tid & 31;
    const int cm = (c + 31) & 31, cp = (c + 1) & 31;
    const int oc0 = obase + ocp * 2;
    float a0 = bs[ocp * 2], a1 = bs[ocp * 2 + 1];
    const float4* w0 = (const float4*)&ws[ocp * 2][0][0];
    const float4* w1 = (const float4*)&ws[ocp * 2 + 1][0][0];

#pragma unroll
    for (int tr = 0; tr < 3; tr++) {
#pragma unroll
        for (int tc = 0; tc < 3; tc++) {
            const int cx = (tc == 0) ? cm : ((tc == 1) ? c : cp);
            const float4* xp  = &xs[(tr * 32 + cx) * 17];
            const float4* wp0 = w0 + (tr * 3 + tc) * 16;
            const float4* wp1 = w1 + (tr * 3 + tc) * 16;
#pragma unroll
            for (int icv = 0; icv < 16; icv++) {
                float4 xv = xp[icv];
                float4 v0 = wp0[icv];
                float4 v1 = wp1[icv];
                a0 = fmaf(xv.x, v0.x, fmaf(xv.y, v0.y, fmaf(xv.z, v0.z, fmaf(xv.w, v0.w, a0))));
                a1 = fmaf(xv.x, v1.x, fmaf(xv.y, v1.y, fmaf(xv.z, v1.z, fmaf(xv.w, v1.w, a1))));
            }
        }
    }
    if (RELU) { a0 = fmaxf(a0, 0.f); a1 = fmaxf(a1, 0.f); }
    const int px = (r0 << 5) + c;
    float2 o; o.x = a0; o.y = a1;
    *(float2*)&y[(size_t)px * OC + oc0] = o;
}

// ---------------- channel-last conv, IC=1 (encoder stage 1) ----------------
// Block = 128 threads = 128 px (4 rows); thread computes 4 oc (float4 store).
__global__ __launch_bounds__(128) void conv1_cl(const float* __restrict__ x,
                                                const float* __restrict__ wgt,
                                                const float* __restrict__ bias,
                                                float* __restrict__ y)
{
    __shared__ float xs[6 * 32];
    __shared__ float ws[4][9];
    __shared__ float bs[4];
    const int tid = threadIdx.x;
    const int obase = blockIdx.y * 4;
    x += blockIdx.z * HW;
    y += (size_t)blockIdx.z * DM * HW;
    const int r0 = blockIdx.x * 4;
    for (int k = tid; k < 6 * 32; k += 128) {
        int lr = k >> 5, c = k & 31;
        xs[k] = x[(((r0 - 1 + lr) & 31) << 5) + c];
    }
    if (tid < 36) ws[tid / 9][tid % 9] = wgt[(obase + tid / 9) * 9 + tid % 9];
    if (tid < 4)  bs[tid] = bias[obase + tid];
    __syncthreads();

    const int hl = tid >> 5, c = tid & 31;
    const int cm = (c + 31) & 31, cp = (c + 1) & 31;
    float xv[9];
#pragma unroll
    for (int tr = 0; tr < 3; tr++) {
        xv[tr * 3 + 0] = xs[(hl + tr) * 32 + cm];
        xv[tr * 3 + 1] = xs[(hl + tr) * 32 + c];
        xv[tr * 3 + 2] = xs[(hl + tr) * 32 + cp];
    }
    float4 o; float* op = &o.x;
#pragma unroll
    for (int j = 0; j < 4; j++) {
        float a = bs[j];
#pragma unroll
        for (int t9 = 0; t9 < 9; t9++) a = fmaf(xv[t9], ws[j][t9], a);
        op[j] = fmaxf(a, 0.f);
    }
    const int px = blockIdx.x * 128 + tid;
    *(float4*)&y[(size_t)px * DM + obase] = o;
}

// ---------------- channel-last conv, OC=1 (decoder out) ----------------
// Block = 128 = 32 px (1 row) x 4 ic-quarters; shfl reduce. grid = 32.
__global__ __launch_bounds__(128) void conv_out(const float* __restrict__ x,
                                                const float* __restrict__ wgt,
                                                const float* __restrict__ bias,
                                                float* __restrict__ y)
{
    __shared__ float4 xs[3 * 32 * 17];
    __shared__ float  ws[9][64];
    const int tid = threadIdx.x;
    const int r0 = blockIdx.x;
    const float4* x4 = (const float4*)x;
    for (int k = tid; k < 3 * 32 * 16; k += 128) {
        int lr = k >> 9; int rem = k & 511; int c = rem >> 4; int icv = rem & 15;
        int row = (r0 - 1 + lr) & 31;
        xs[(lr * 32 + c) * 17 + icv] = x4[(((row << 5) + c) << 4) + icv];
    }
    for (int k = tid; k < 576; k += 128) {
        int tap = k >> 6, ic = k & 63;
        ws[tap][ic] = wgt[ic * 9 + tap];
    }
    __syncthreads();

    const int icq = tid & 3, c = tid >> 2;   // c = 0..31
    const int cm = (c + 31) & 31, cp = (c + 1) & 31;
    float acc = 0.f;
#pragma unroll
    for (int tr = 0; tr < 3; tr++) {
#pragma unroll
        for (int tc = 0; tc < 3; tc++) {
            const int cx = (tc == 0) ? cm : ((tc == 1) ? c : cp);
            const float4* xp = &xs[(tr * 32 + cx) * 17];
            const float4* wp = (const float4*)&ws[tr * 3 + tc][0];
#pragma unroll
            for (int k = 0; k < 4; k++) {
                float4 xv = xp[icq * 4 + k];
                float4 wv = wp[icq * 4 + k];
                acc = fmaf(xv.x, wv.x, fmaf(xv.y, wv.y, fmaf(xv.z, wv.z, fmaf(xv.w, wv.w, acc))));
            }
        }
    }
    acc += __shfl_xor_sync(0xffffffffu, acc, 1);
    acc += __shfl_xor_sync(0xffffffffu, acc, 2);
    if (icq == 0) y[(r0 << 5) + c] = acc + bias[0];
}

// ---------------- fused SSM cell step (drifting frame, in-place state) ----------------
// Block = 128 = 2 px x 64 d (warp = 32 d, coalesced 128B state lines). grid = 512.
template <bool FIRST, bool DOY>
__global__ __launch_bounds__(128) void cell_step(const float* __restrict__ u,
                                                 const float* __restrict__ cc,
                                                 const float* __restrict__ Dskip,
                                                 const float* __restrict__ dtp,
                                                 int tau, float* __restrict__ ymax)
{
    const int tid = threadIdx.x;
    const int d = tid & 63;
    const int p = blockIdx.x * 2 + (tid >> 6);
    const int h = p >> 5, w = p & 31;

    float xx = cc[p * 96 + d] + dtp[0];
    float delta = (xx > 20.f) ? xx : log1pf(expf(xx));   // softplus
    const float ud = u[p * 64 + d];

    float ab[DS], bu[DS], cv[DS];
#pragma unroll
    for (int n = 0; n < DS; n++) {
        float a = g_A[n * 64 + d];
        float e = __expf(delta * a);
        ab[n] = e;
        bu[n] = (e - 1.f) * g_rA[n * 64 + d] * cc[p * 96 + 64 + n] * ud;  // broadcast loads
        if (DOY) cv[n] = cc[p * 96 + 80 + n];
    }

    float best = -1e30f;
#pragma unroll 1
    for (int v = 0; v < NV; v++) {
        int v5 = v / 5;
        int vx = v5 - 2;
        int vy = (v - v5 * 5) - 2;
        int qh = (h + tau * vy) & 31;
        int qw = (w + tau * vx) & 31;
        float* sp = g_state + (((size_t)v * DS * HW) + (size_t)((qh << 5) + qw)) * 64 + d;
        float acc = 0.f;
#pragma unroll
        for (int n = 0; n < DS; n++) {
            float s = FIRST ? bu[n] : fmaf(ab[n], sp[(size_t)n * HW * 64], bu[n]);
            sp[(size_t)n * HW * 64] = s;
            if (DOY) acc = fmaf(s, cv[n], acc);
        }
        if (DOY) best = fmaxf(best, acc);
    }
    if (DOY) ymax[p * 64 + d] = fmaf(Dskip[d], ud, best);
}

// ---------------- launch ----------------
extern "C" void kernel_launch(void* const* d_in, const int* in_sizes, int n_in,
                              void* d_out, int out_size)
{
    const float* input_seq = (const float*)d_in[0];
    const float* enc_w1 = (const float*)d_in[1];
    const float* enc_b1 = (const float*)d_in[2];
    const float* enc_w2 = (const float*)d_in[3];
    const float* enc_b2 = (const float*)d_in[4];
    const float* wd     = (const float*)d_in[5];
    const float* bd     = (const float*)d_in[6];
    const float* wB     = (const float*)d_in[7];
    const float* wC     = (const float*)d_in[8];
    const float* logA   = (const float*)d_in[9];
    const float* Dskip  = (const float*)d_in[10];
    const float* dt_inv = (const float*)d_in[11];
    const float* dec_w1 = (const float*)d_in[12];
    const float* dec_b1 = (const float*)d_in[13];
    const float* dec_w2 = (const float*)d_in[14];
    const float* dec_b2 = (const float*)d_in[15];
    const float* dec_w3 = (const float*)d_in[16];
    const float* dec_b3 = (const float*)d_in[17];
    float* out = (float*)d_out;

    float *p_u, *p_e1, *p_cc, *p_wpack, *p_bpack, *p_ymax, *p_d1, *p_d2;
    cudaGetSymbolAddress((void**)&p_u, g_u);
    cudaGetSymbolAddress((void**)&p_e1, g_e1);
    cudaGetSymbolAddress((void**)&p_cc, g_cc);
    cudaGetSymbolAddress((void**)&p_wpack, g_wpack);
    cudaGetSymbolAddress((void**)&p_bpack, g_bpack);
    cudaGetSymbolAddress((void**)&p_ymax, g_ymax);
    cudaGetSymbolAddress((void**)&p_d1, g_d1);
    cudaGetSymbolAddress((void**)&p_d2, g_d2);

    // pack weights + A fields
    pack_w<<<216, 256>>>(wd, bd, wB, wC, logA);

    // ---- encode: batched over 4 frames ----
    conv1_cl<<<dim3(8, 16, TIN), 128>>>(input_seq, enc_w1, enc_b1, p_e1);
    conv_cl<true><<<dim3(32, 16, TIN), 64>>>(p_e1, enc_w2, enc_b2, p_u, DM);
    conv_cl<false><<<dim3(32, 24, TIN), 64>>>(p_u, p_wpack, p_bpack, p_cc, 96);
    for (int t = 0; t < TIN; t++) {
        const float* ut = p_u + (size_t)t * HW * DM;
        const float* ct = p_cc + (size_t)t * HW * 96;
        if (t == 0)
            cell_step<true, false><<<512, 128>>>(ut, ct, Dskip, dt_inv, 1, nullptr);
        else
            cell_step<false, false><<<512, 128>>>(ut, ct, Dskip, dt_inv, t + 1, nullptr);
    }

    // ---- decode ----
    int steps = out_size / HW;
    for (int t = 0; t < steps; t++) {
        const float* src = (t == 0) ? (input_seq + 3 * HW) : (out + (size_t)(t - 1) * HW);
        conv1_cl<<<dim3(8, 16, 1), 128>>>(src, enc_w1, enc_b1, p_e1);
        conv_cl<true><<<dim3(32, 16, 1), 64>>>(p_e1, enc_w2, enc_b2, p_u, DM);
        conv_cl<false><<<dim3(32, 24, 1), 64>>>(p_u, p_wpack, p_bpack, p_cc, 96);
        cell_step<false, true><<<512, 128>>>(p_u, p_cc, Dskip, dt_inv, TIN + 1 + t, p_ymax);
        conv_cl<true><<<dim3(32, 16, 1), 64>>>(p_ymax, dec_w1, dec_b1, p_d1, DM);
        conv_cl<true><<<dim3(32, 16, 1), 64>>>(p_d1, dec_w2, dec_b2, p_d2, DM);
        conv_out<<<32, 128>>>(p_d2, dec_w3, dec_b3, out + (size_t)t * HW);
    }
}